// round 1
// baseline (speedup 1.0000x reference)
#include <cuda_runtime.h>
#include <cuda_bf16.h>
#include <math.h>

// ---------------- problem dims ----------------
#define NB 2
#define HH 64
#define WW 64
#define DD 256
#define SS 16
#define NHD 4
#define HDIM 64
#define MLPH 1024
#define NPOS (NB*HH*WW)          // 8192
#define NKV  (NPOS*SS)           // 131072

// ---------------- scratch (device globals; no allocations allowed) -------
__device__ float g_kv[(size_t)NKV * DD];     // sampled kv    [131072,256]
__device__ float g_q [(size_t)NPOS * DD];    // queries       [8192,256]
__device__ float g_K [(size_t)NKV * DD];     // keys          [131072,256]
__device__ float g_V [(size_t)NKV * DD];     // values        [131072,256]
__device__ float g_x [(size_t)NPOS * DD];    // post-LN1      [8192,256]
__device__ float g_h1[(size_t)NPOS * MLPH];  // mlp hidden    [8192,1024]
__device__ float g_y [(size_t)NPOS * DD];    // pre-LN2       [8192,256]

// ---------------- helpers ----------------
__device__ __forceinline__ float blk_sum256(float v, float* red) {
    int t = threadIdx.x;
    red[t] = v; __syncthreads();
    #pragma unroll
    for (int o = 128; o > 0; o >>= 1) {
        if (t < o) red[t] += red[t + o];
        __syncthreads();
    }
    float r = red[0]; __syncthreads();
    return r;
}

__device__ __forceinline__ float gelu_tanh(float x) {
    const float c = 0.7978845608028654f;
    float t = tanhf(c * (x + 0.044715f * x * x * x));
    return 0.5f * x * (1.f + t);
}

// ============================================================
// K1: offsets -> sampling loc -> bilinear gather -> kv ; plus Q projection
// grid 2048 blocks x 256 thr, 4 positions per block
// ============================================================
__global__ __launch_bounds__(256)
void k1_sample(const float* __restrict__ hs, const float* __restrict__ emb,
               const float* __restrict__ Woff, const float* __restrict__ boff,
               const float* __restrict__ Wkvp, const float* __restrict__ bkvp,
               const float* __restrict__ Wq,  const float* __restrict__ bq) {
    __shared__ float s_hs[DD];
    __shared__ float s_off[2 * SS];
    __shared__ float s_w[SS][4];
    __shared__ int   s_idx[SS][4];
    int tid = threadIdx.x;

    float wkvp0 = Wkvp[tid];
    float wkvp1 = Wkvp[DD + tid];
    float bkv   = bkvp[tid];
    float bqv   = bq[tid];

    for (int pp = 0; pp < 4; ++pp) {
        int p  = blockIdx.x * 4 + pp;
        int n  = p >> 12;           // /(64*64)
        int ij = p & 4095;
        int iy = ij >> 6, jx = ij & 63;

        s_hs[tid] = hs[(size_t)p * DD + tid];
        __syncthreads();

        if (tid < 32) {
            float acc = boff[tid];
            #pragma unroll 8
            for (int d = 0; d < DD; ++d) acc += s_hs[d] * Woff[d * 32 + tid];
            float sg = 1.f / (1.f + expf(-acc));
            s_off[tid] = 60.f * sg - 30.f;
        }
        __syncthreads();

        if (tid < SS) {
            int s = tid;
            float y = fminf(fmaxf((float)iy + s_off[2*s    ], 0.f), 63.f);
            float x = fminf(fmaxf((float)jx + s_off[2*s + 1], 0.f), 63.f);
            float y0f = floorf(y), x0f = floorf(x);
            int y0 = (int)y0f, x0 = (int)x0f;
            int y1 = min(y0 + 1, 63), x1 = min(x0 + 1, 63);
            float wy = y - y0f, wx = x - x0f;
            s_w[s][0] = (1.f - wy) * (1.f - wx);
            s_w[s][1] = (1.f - wy) * wx;
            s_w[s][2] = wy * (1.f - wx);
            s_w[s][3] = wy * wx;
            int base = n * 4096;
            s_idx[s][0] = (base + y0 * 64 + x0) * DD;
            s_idx[s][1] = (base + y0 * 64 + x1) * DD;
            s_idx[s][2] = (base + y1 * 64 + x0) * DD;
            s_idx[s][3] = (base + y1 * 64 + x1) * DD;
        }
        __syncthreads();

        // kv gather + offset embedding
        #pragma unroll 4
        for (int s = 0; s < SS; ++s) {
            float v = s_w[s][0] * emb[s_idx[s][0] + tid]
                    + s_w[s][1] * emb[s_idx[s][1] + tid]
                    + s_w[s][2] * emb[s_idx[s][2] + tid]
                    + s_w[s][3] * emb[s_idx[s][3] + tid];
            v += s_off[2*s] * wkvp0 + s_off[2*s + 1] * wkvp1 + bkv;
            g_kv[((size_t)p * SS + s) * DD + tid] = v;
        }

        // Q projection: q[ae] = sum_d hs[d] * Wq[d][ae]
        float acc = bqv;
        #pragma unroll 8
        for (int d = 0; d < DD; ++d) acc += s_hs[d] * Wq[d * DD + tid];
        g_q[(size_t)p * DD + tid] = acc;
        __syncthreads();
    }
}

// ============================================================
// K2: K = kv@Wk + bk ; V = kv@Wv + bv   (fused, shared A reads)
// M=131072, N=256, K=256. Tiles 64x64x16, 256 thr, 4x4 per thread.
// grid (2048, 4)
// ============================================================
__global__ __launch_bounds__(256)
void k2_gemm_kv(const float* __restrict__ Wk, const float* __restrict__ Wv,
                const float* __restrict__ bk, const float* __restrict__ bv) {
    __shared__ float As [16][64];
    __shared__ float Bks[16][64];
    __shared__ float Bvs[16][64];
    int tid = threadIdx.x;
    int tx = tid & 15, ty = tid >> 4;
    int rowBase = blockIdx.x * 64;
    int colBase = blockIdx.y * 64;

    float accK[4][4] = {}, accV[4][4] = {};

    for (int k0 = 0; k0 < DD; k0 += 16) {
        {   // A tile: 64x16
            int m = tid >> 2, kq = (tid & 3) * 4;
            float4 a = *(const float4*)&g_kv[(size_t)(rowBase + m) * DD + k0 + kq];
            As[kq    ][m] = a.x; As[kq + 1][m] = a.y;
            As[kq + 2][m] = a.z; As[kq + 3][m] = a.w;
            // B tiles: 16x64
            int kb = tid >> 4, nq = (tid & 15) * 4;
            *(float4*)&Bks[kb][nq] = *(const float4*)&Wk[(size_t)(k0 + kb) * DD + colBase + nq];
            *(float4*)&Bvs[kb][nq] = *(const float4*)&Wv[(size_t)(k0 + kb) * DD + colBase + nq];
        }
        __syncthreads();
        #pragma unroll
        for (int k = 0; k < 16; ++k) {
            float4 a4 = *(float4*)&As [k][ty * 4];
            float4 b4 = *(float4*)&Bks[k][tx * 4];
            float4 c4 = *(float4*)&Bvs[k][tx * 4];
            float av[4] = {a4.x, a4.y, a4.z, a4.w};
            float bb[4] = {b4.x, b4.y, b4.z, b4.w};
            float cc[4] = {c4.x, c4.y, c4.z, c4.w};
            #pragma unroll
            for (int i = 0; i < 4; ++i)
                #pragma unroll
                for (int j = 0; j < 4; ++j) {
                    accK[i][j] += av[i] * bb[j];
                    accV[i][j] += av[i] * cc[j];
                }
        }
        __syncthreads();
    }

    #pragma unroll
    for (int i = 0; i < 4; ++i) {
        int row = rowBase + ty * 4 + i;
        #pragma unroll
        for (int j = 0; j < 4; ++j) {
            int col = colBase + tx * 4 + j;
            g_K[(size_t)row * DD + col] = accK[i][j] + bk[col];
            g_V[(size_t)row * DD + col] = accV[i][j] + bv[col];
        }
    }
}

// ============================================================
// K3: attention (1 query vs 16 kv per pos) + out proj + residual + LN1
// grid 2048 x 256 thr, 4 positions per block
// ============================================================
__global__ __launch_bounds__(256)
void k3_attn(const float* __restrict__ hs, const float* __restrict__ Wo,
             const float* __restrict__ bo,
             const float* __restrict__ ln1s, const float* __restrict__ ln1b) {
    __shared__ float s_q[DD];
    __shared__ float s_sc[NHD * SS];   // [a*16+s]
    __shared__ float s_p [NHD * SS];
    __shared__ float s_attn[DD];
    __shared__ float s_red[DD];
    int tid = threadIdx.x;

    for (int pp = 0; pp < 4; ++pp) {
        int p = blockIdx.x * 4 + pp;
        s_q[tid] = g_q[(size_t)p * DD + tid];
        __syncthreads();

        if (tid < NHD * SS) {
            int a = tid >> 4, s = tid & 15;
            const float* krow = &g_K[((size_t)p * SS + s) * DD + a * HDIM];
            const float* qrow = &s_q[a * HDIM];
            float acc = 0.f;
            #pragma unroll 16
            for (int e = 0; e < HDIM; ++e) acc += qrow[e] * krow[e];
            s_sc[tid] = acc * 0.125f;   // 1/sqrt(64)
        }
        __syncthreads();

        if (tid < NHD) {
            int a = tid;
            float mx = -1e30f;
            #pragma unroll
            for (int s = 0; s < SS; ++s) mx = fmaxf(mx, s_sc[a * SS + s]);
            float sum = 0.f;
            #pragma unroll
            for (int s = 0; s < SS; ++s) {
                float e = expf(s_sc[a * SS + s] - mx);
                s_p[a * SS + s] = e; sum += e;
            }
            float inv = 1.f / sum;
            #pragma unroll
            for (int s = 0; s < SS; ++s) s_p[a * SS + s] *= inv;
        }
        __syncthreads();

        // attn[ae] = sum_s p[a][s] * V[s][ae]
        {
            int a = tid >> 6;
            float acc = 0.f;
            #pragma unroll
            for (int s = 0; s < SS; ++s)
                acc += s_p[a * SS + s] * g_V[((size_t)p * SS + s) * DD + tid];
            s_attn[tid] = acc;
        }
        __syncthreads();

        // out proj: o[d] = sum_ae attn[ae] * Wo[ae][d]
        float o = bo[tid];
        #pragma unroll 8
        for (int ae = 0; ae < DD; ++ae) o += s_attn[ae] * Wo[(size_t)ae * DD + tid];

        float x = hs[(size_t)p * DD + tid] + o;
        float sum  = blk_sum256(x, s_red);
        float sum2 = blk_sum256(x * x, s_red);
        float mean = sum * (1.f / DD);
        float var  = sum2 * (1.f / DD) - mean * mean;
        float xn = (x - mean) * rsqrtf(var + 1e-6f) * ln1s[tid] + ln1b[tid];
        g_x[(size_t)p * DD + tid] = xn;
        __syncthreads();
    }
}

// ============================================================
// K4: fc1  h1 = gelu(x @ W1 + b1)   M=8192,N=1024,K=256  grid(128,16)
// ============================================================
__global__ __launch_bounds__(256)
void k4_fc1(const float* __restrict__ W1, const float* __restrict__ b1) {
    __shared__ float As[16][64];
    __shared__ float Bs[16][64];
    int tid = threadIdx.x;
    int tx = tid & 15, ty = tid >> 4;
    int rowBase = blockIdx.x * 64;
    int colBase = blockIdx.y * 64;
    float acc[4][4] = {};

    for (int k0 = 0; k0 < DD; k0 += 16) {
        int m = tid >> 2, kq = (tid & 3) * 4;
        float4 a = *(const float4*)&g_x[(size_t)(rowBase + m) * DD + k0 + kq];
        As[kq][m] = a.x; As[kq+1][m] = a.y; As[kq+2][m] = a.z; As[kq+3][m] = a.w;
        int kb = tid >> 4, nq = (tid & 15) * 4;
        *(float4*)&Bs[kb][nq] = *(const float4*)&W1[(size_t)(k0 + kb) * MLPH + colBase + nq];
        __syncthreads();
        #pragma unroll
        for (int k = 0; k < 16; ++k) {
            float4 a4 = *(float4*)&As[k][ty * 4];
            float4 b4 = *(float4*)&Bs[k][tx * 4];
            float av[4] = {a4.x, a4.y, a4.z, a4.w};
            float bb[4] = {b4.x, b4.y, b4.z, b4.w};
            #pragma unroll
            for (int i = 0; i < 4; ++i)
                #pragma unroll
                for (int j = 0; j < 4; ++j) acc[i][j] += av[i] * bb[j];
        }
        __syncthreads();
    }
    #pragma unroll
    for (int i = 0; i < 4; ++i) {
        int row = rowBase + ty * 4 + i;
        #pragma unroll
        for (int j = 0; j < 4; ++j) {
            int col = colBase + tx * 4 + j;
            g_h1[(size_t)row * MLPH + col] = gelu_tanh(acc[i][j] + b1[col]);
        }
    }
}

// ============================================================
// K5: fc2  y = x + h1 @ W2 + b2   M=8192,N=256,K=1024  grid(128,4)
// ============================================================
__global__ __launch_bounds__(256)
void k5_fc2(const float* __restrict__ W2, const float* __restrict__ b2) {
    __shared__ float As[16][64];
    __shared__ float Bs[16][64];
    int tid = threadIdx.x;
    int tx = tid & 15, ty = tid >> 4;
    int rowBase = blockIdx.x * 64;
    int colBase = blockIdx.y * 64;
    float acc[4][4] = {};

    for (int k0 = 0; k0 < MLPH; k0 += 16) {
        int m = tid >> 2, kq = (tid & 3) * 4;
        float4 a = *(const float4*)&g_h1[(size_t)(rowBase + m) * MLPH + k0 + kq];
        As[kq][m] = a.x; As[kq+1][m] = a.y; As[kq+2][m] = a.z; As[kq+3][m] = a.w;
        int kb = tid >> 4, nq = (tid & 15) * 4;
        *(float4*)&Bs[kb][nq] = *(const float4*)&W2[(size_t)(k0 + kb) * DD + colBase + nq];
        __syncthreads();
        #pragma unroll
        for (int k = 0; k < 16; ++k) {
            float4 a4 = *(float4*)&As[k][ty * 4];
            float4 b4 = *(float4*)&Bs[k][tx * 4];
            float av[4] = {a4.x, a4.y, a4.z, a4.w};
            float bb[4] = {b4.x, b4.y, b4.z, b4.w};
            #pragma unroll
            for (int i = 0; i < 4; ++i)
                #pragma unroll
                for (int j = 0; j < 4; ++j) acc[i][j] += av[i] * bb[j];
        }
        __syncthreads();
    }
    #pragma unroll
    for (int i = 0; i < 4; ++i) {
        int row = rowBase + ty * 4 + i;
        #pragma unroll
        for (int j = 0; j < 4; ++j) {
            int col = colBase + tx * 4 + j;
            g_y[(size_t)row * DD + col] =
                acc[i][j] + b2[col] + g_x[(size_t)row * DD + col];
        }
    }
}

// ============================================================
// K6: final LayerNorm (ln2) -> output
// ============================================================
__global__ __launch_bounds__(256)
void k6_ln2(const float* __restrict__ ln2s, const float* __restrict__ ln2b,
            float* __restrict__ out) {
    __shared__ float s_red[DD];
    int tid = threadIdx.x;
    for (int pp = 0; pp < 4; ++pp) {
        int p = blockIdx.x * 4 + pp;
        float x = g_y[(size_t)p * DD + tid];
        float sum  = blk_sum256(x, s_red);
        float sum2 = blk_sum256(x * x, s_red);
        float mean = sum * (1.f / DD);
        float var  = sum2 * (1.f / DD) - mean * mean;
        out[(size_t)p * DD + tid] =
            (x - mean) * rsqrtf(var + 1e-6f) * ln2s[tid] + ln2b[tid];
        __syncthreads();
    }
}

// ============================================================
extern "C" void kernel_launch(void* const* d_in, const int* in_sizes, int n_in,
                              void* d_out, int out_size) {
    const float* hs    = (const float*)d_in[0];
    const float* emb   = (const float*)d_in[1];
    const float* Woff  = (const float*)d_in[2];
    const float* boff  = (const float*)d_in[3];
    const float* Wkvp  = (const float*)d_in[4];
    const float* bkvp  = (const float*)d_in[5];
    const float* Wq    = (const float*)d_in[6];
    const float* bq    = (const float*)d_in[7];
    const float* Wk    = (const float*)d_in[8];
    const float* bk    = (const float*)d_in[9];
    const float* Wv    = (const float*)d_in[10];
    const float* bv    = (const float*)d_in[11];
    const float* Wo    = (const float*)d_in[12];
    const float* bo    = (const float*)d_in[13];
    const float* ln1s  = (const float*)d_in[14];
    const float* ln1b  = (const float*)d_in[15];
    const float* ln2s  = (const float*)d_in[16];
    const float* ln2b  = (const float*)d_in[17];
    const float* W1    = (const float*)d_in[18];
    const float* b1    = (const float*)d_in[19];
    const float* W2    = (const float*)d_in[20];
    const float* b2    = (const float*)d_in[21];
    float* out = (float*)d_out;

    k1_sample<<<NPOS / 4, 256>>>(hs, emb, Woff, boff, Wkvp, bkvp, Wq, bq);
    k2_gemm_kv<<<dim3(NKV / 64, DD / 64), 256>>>(Wk, Wv, bk, bv);
    k3_attn<<<NPOS / 4, 256>>>(hs, Wo, bo, ln1s, ln1b);
    k4_fc1<<<dim3(NPOS / 64, MLPH / 64), 256>>>(W1, b1);
    k5_fc2<<<dim3(NPOS / 64, DD / 64), 256>>>(W2, b2);
    k6_ln2<<<NPOS / 4, 256>>>(ln2s, ln2b, out);
}

// round 5
// speedup vs baseline: 2.6241x; 2.6241x over previous
#include <cuda_runtime.h>
#include <cuda_bf16.h>
#include <math.h>

// ---------------- problem dims ----------------
#define NB 2
#define HH 64
#define WW 64
#define DD 256
#define SS 16
#define NHD 4
#define HDIM 64
#define MLPH 1024
#define NPOS (NB*HH*WW)          // 8192
#define NKV  (NPOS*SS)           // 131072

// ---------------- scratch (device globals; no allocations allowed) -------
__device__ __align__(256) float g_kv  [(size_t)NKV * DD];     // sampled kv [131072,256]
__device__ __align__(256) float g_off [(size_t)NPOS * 32];    // transformed offsets
__device__ __align__(256) float g_q   [(size_t)NPOS * DD];    // queries [8192,256]
__device__ __align__(256) float g_WkT [4 * HDIM * DD];        // Wk transposed per head
__device__ __align__(256) float g_qk  [(size_t)NPOS * 4 * DD];// folded q·Wk^T [8192,1024]
__device__ __align__(256) float g_pkv [(size_t)NPOS * 4 * DD];// p-weighted kv [8192,1024]
__device__ __align__(256) float g_attn[(size_t)NPOS * DD];    // attn pre-Wo [8192,256]
__device__ __align__(256) float g_o   [(size_t)NPOS * DD];    // attn out [8192,256]
__device__ __align__(256) float g_x   [(size_t)NPOS * DD];    // post-LN1
__device__ __align__(256) float g_h1  [(size_t)NPOS * MLPH];  // mlp hidden
__device__ __align__(256) float g_y   [(size_t)NPOS * DD];    // pre-LN2

// ---------------- helpers ----------------
__device__ __forceinline__ float blk_sum256(float v, float* red) {
    int t = threadIdx.x;
    red[t] = v; __syncthreads();
    #pragma unroll
    for (int o = 128; o > 0; o >>= 1) {
        if (t < o) red[t] += red[t + o];
        __syncthreads();
    }
    float r = red[0]; __syncthreads();
    return r;
}

__device__ __forceinline__ float gelu_tanh(float x) {
    const float c = 0.7978845608028654f;
    float t = tanhf(c * (x + 0.044715f * x * x * x));
    return 0.5f * x * (1.f + t);
}

// ============================================================
// K0: transpose Wk[d, a, e] -> WkT[a][e][d]
// ============================================================
__global__ __launch_bounds__(256)
void k_transpose_wk(const float* __restrict__ Wk) {
    int o = blockIdx.x * 256 + threadIdx.x;      // 65536 total
    int d = o & 255, e = (o >> 8) & 63, a = o >> 14;
    g_WkT[o] = Wk[d * 256 + a * 64 + e];
}

// ============================================================
// K_off: offsets = 60*sigmoid(hs@Woff + boff) - 30  -> g_off [8192,32]
// warp per position, lane = output column
// ============================================================
__global__ __launch_bounds__(256)
void k_off(const float* __restrict__ hs, const float* __restrict__ Woff,
           const float* __restrict__ boff) {
    int w = threadIdx.x >> 5, j = threadIdx.x & 31;
    int p = blockIdx.x * 8 + w;
    float hreg[8];
    #pragma unroll
    for (int i = 0; i < 8; ++i) hreg[i] = hs[(size_t)p * 256 + i * 32 + j];
    float acc = 0.f;
    #pragma unroll
    for (int i = 0; i < 8; ++i)
        #pragma unroll
        for (int l = 0; l < 32; ++l) {
            float h = __shfl_sync(0xffffffffu, hreg[i], l);
            acc += h * Woff[(i * 32 + l) * 32 + j];
        }
    float sg = 1.f / (1.f + expf(-(acc + boff[j])));
    g_off[(size_t)p * 32 + j] = 60.f * sg - 30.f;
}

// ============================================================
// K_gather: bilinear gather + offset embedding -> g_kv
// ============================================================
__global__ __launch_bounds__(256)
void k_gather(const float* __restrict__ emb, const float* __restrict__ Wkvp,
              const float* __restrict__ bkvp) {
    __shared__ float s_off[32];
    __shared__ float s_w[SS][4];
    __shared__ int   s_idx[SS][4];
    int tid = threadIdx.x;
    float wkvp0 = Wkvp[tid];
    float wkvp1 = Wkvp[DD + tid];
    float bkv   = bkvp[tid];

    for (int pp = 0; pp < 4; ++pp) {
        int p  = blockIdx.x * 4 + pp;
        int n  = p >> 12;
        int iy = (p >> 6) & 63, jx = p & 63;

        if (tid < 32) s_off[tid] = g_off[(size_t)p * 32 + tid];
        __syncthreads();

        if (tid < SS) {
            int s = tid;
            float y = fminf(fmaxf((float)iy + s_off[2*s    ], 0.f), 63.f);
            float x = fminf(fmaxf((float)jx + s_off[2*s + 1], 0.f), 63.f);
            float y0f = floorf(y), x0f = floorf(x);
            int y0 = (int)y0f, x0 = (int)x0f;
            int y1 = min(y0 + 1, 63), x1 = min(x0 + 1, 63);
            float wy = y - y0f, wx = x - x0f;
            s_w[s][0] = (1.f - wy) * (1.f - wx);
            s_w[s][1] = (1.f - wy) * wx;
            s_w[s][2] = wy * (1.f - wx);
            s_w[s][3] = wy * wx;
            int base = n * 4096;
            s_idx[s][0] = (base + y0 * 64 + x0) * DD;
            s_idx[s][1] = (base + y0 * 64 + x1) * DD;
            s_idx[s][2] = (base + y1 * 64 + x0) * DD;
            s_idx[s][3] = (base + y1 * 64 + x1) * DD;
        }
        __syncthreads();

        #pragma unroll 4
        for (int s = 0; s < SS; ++s) {
            float v = s_w[s][0] * emb[s_idx[s][0] + tid]
                    + s_w[s][1] * emb[s_idx[s][1] + tid]
                    + s_w[s][2] * emb[s_idx[s][2] + tid]
                    + s_w[s][3] * emb[s_idx[s][3] + tid];
            v += s_off[2*s] * wkvp0 + s_off[2*s + 1] * wkvp1 + bkv;
            g_kv[((size_t)p * SS + s) * DD + tid] = v;
        }
        __syncthreads();
    }
}

// ============================================================
// Generic 64x64 tiled GEMM, K-chunk 32, 256 thr, 4x4 per thread.
// C = A@B (+bias) (+res), optional gelu. blockIdx.z = head (strided).
// EPI: 0 = (+bias), 1 = gelu(+bias), 2 = +bias+res
// ============================================================
template<int KTOT, int EPI>
__global__ __launch_bounds__(256)
void gemm_t(const float* __restrict__ A, int lda, long headA,
            const float* __restrict__ B, int ldb, long headB,
            float* __restrict__ C, int ldc, long headC,
            const float* __restrict__ bias, int headBias,
            const float* __restrict__ res, int ldres) {
    A += (long)blockIdx.z * headA;
    B += (long)blockIdx.z * headB;
    C += (long)blockIdx.z * headC;
    if (bias) bias += (long)blockIdx.z * headBias;

    __shared__ float As[32][64];
    __shared__ float Bs[32][64];
    int tid = threadIdx.x;
    int tx = tid & 15, ty = tid >> 4;
    long rowBase = (long)blockIdx.x * 64;
    int  colBase = blockIdx.y * 64;
    float acc[4][4] = {};

    #pragma unroll 1
    for (int k0 = 0; k0 < KTOT; k0 += 32) {
        #pragma unroll
        for (int i = 0; i < 2; ++i) {
            int idx = tid + 256 * i;
            int m = idx >> 3, kq = (idx & 7) * 4;
            float4 a = *(const float4*)&A[(rowBase + m) * lda + k0 + kq];
            As[kq][m] = a.x; As[kq + 1][m] = a.y;
            As[kq + 2][m] = a.z; As[kq + 3][m] = a.w;
            int kb = idx >> 4, nq = (idx & 15) * 4;
            *(float4*)&Bs[kb][nq] =
                *(const float4*)&B[(long)(k0 + kb) * ldb + colBase + nq];
        }
        __syncthreads();
        #pragma unroll
        for (int k = 0; k < 32; ++k) {
            float4 a4 = *(float4*)&As[k][ty * 4];
            float4 b4 = *(float4*)&Bs[k][tx * 4];
            float av[4] = {a4.x, a4.y, a4.z, a4.w};
            float bb[4] = {b4.x, b4.y, b4.z, b4.w};
            #pragma unroll
            for (int i = 0; i < 4; ++i)
                #pragma unroll
                for (int j = 0; j < 4; ++j) acc[i][j] += av[i] * bb[j];
        }
        __syncthreads();
    }

    #pragma unroll
    for (int i = 0; i < 4; ++i) {
        long row = rowBase + ty * 4 + i;
        #pragma unroll
        for (int j = 0; j < 4; ++j) {
            int col = colBase + tx * 4 + j;
            float v = acc[i][j] + (bias ? bias[col] : 0.f);
            if (EPI == 1) v = gelu_tanh(v);
            if (EPI == 2) v += res[row * ldres + col];
            C[row * ldc + col] = v;
        }
    }
}

// ============================================================
// K_core: per-position scores = qk . kv, softmax, pkv = p @ kv
// ============================================================
__global__ __launch_bounds__(256)
void k_core() {
    __shared__ float s_kv[16 * 258];
    __shared__ float s_qk[1024];
    __shared__ float s_sc[64];
    __shared__ float s_p[64];
    int t = threadIdx.x;

    for (int pp = 0; pp < 4; ++pp) {
        size_t p = (size_t)blockIdx.x * 4 + pp;
        #pragma unroll
        for (int i = 0; i < 16; ++i)
            s_kv[i * 258 + t] = g_kv[(p * 16 + i) * 256 + t];
        #pragma unroll
        for (int i = 0; i < 4; ++i)
            s_qk[i * 256 + t] = g_qk[p * 1024 + i * 256 + t];
        __syncthreads();

        if (t < 64) {
            int a = t >> 4, s = t & 15;
            const float* kvp = &s_kv[s * 258];
            const float* qkp = &s_qk[a * 256];
            float acc = 0.f;
            #pragma unroll 8
            for (int d = 0; d < 256; ++d) acc += kvp[d] * qkp[d];
            s_sc[t] = acc * 0.125f;
        }
        __syncthreads();

        if (t < 4) {
            float mx = -1e30f;
            #pragma unroll
            for (int s = 0; s < 16; ++s) mx = fmaxf(mx, s_sc[t * 16 + s]);
            float sum = 0.f;
            float e[16];
            #pragma unroll
            for (int s = 0; s < 16; ++s) { e[s] = expf(s_sc[t * 16 + s] - mx); sum += e[s]; }
            float inv = 1.f / sum;
            #pragma unroll
            for (int s = 0; s < 16; ++s) s_p[t * 16 + s] = e[s] * inv;
        }
        __syncthreads();

        #pragma unroll
        for (int a = 0; a < 4; ++a) {
            float acc = 0.f;
            #pragma unroll
            for (int s = 0; s < 16; ++s)
                acc += s_p[a * 16 + s] * s_kv[s * 258 + t];
            g_pkv[p * 1024 + a * 256 + t] = acc;
        }
        __syncthreads();
    }
}

// ============================================================
// K_ln: out = LN(xin (+ addin)) * sc + bi      (4 rows per block)
// ============================================================
__global__ __launch_bounds__(256)
void k_ln(const float* __restrict__ xin, const float* __restrict__ addin,
          const float* __restrict__ sc, const float* __restrict__ bi,
          float* __restrict__ out) {
    __shared__ float red[256];
    int t = threadIdx.x;
    for (int pp = 0; pp < 4; ++pp) {
        size_t p = (size_t)blockIdx.x * 4 + pp;
        float x = xin[p * 256 + t];
        if (addin) x += addin[p * 256 + t];
        float sum  = blk_sum256(x, red);
        float sum2 = blk_sum256(x * x, red);
        float mean = sum * (1.f / 256.f);
        float var  = sum2 * (1.f / 256.f) - mean * mean;
        out[p * 256 + t] = (x - mean) * rsqrtf(var + 1e-6f) * sc[t] + bi[t];
    }
}

// ============================================================
extern "C" void kernel_launch(void* const* d_in, const int* in_sizes, int n_in,
                              void* d_out, int out_size) {
    const float* hs    = (const float*)d_in[0];
    const float* emb   = (const float*)d_in[1];
    const float* Woff  = (const float*)d_in[2];
    const float* boff  = (const float*)d_in[3];
    const float* Wkvp  = (const float*)d_in[4];
    const float* bkvp  = (const float*)d_in[5];
    const float* Wq    = (const float*)d_in[6];
    const float* bq    = (const float*)d_in[7];
    const float* Wk    = (const float*)d_in[8];
    const float* bk    = (const float*)d_in[9];   (void)bk; // softmax-invariant, folded out
    const float* Wv    = (const float*)d_in[10];
    const float* bv    = (const float*)d_in[11];
    const float* Wo    = (const float*)d_in[12];
    const float* bo    = (const float*)d_in[13];
    const float* ln1s  = (const float*)d_in[14];
    const float* ln1b  = (const float*)d_in[15];
    const float* ln2s  = (const float*)d_in[16];
    const float* ln2b  = (const float*)d_in[17];
    const float* W1    = (const float*)d_in[18];
    const float* b1    = (const float*)d_in[19];
    const float* W2    = (const float*)d_in[20];
    const float* b2    = (const float*)d_in[21];
    float* out = (float*)d_out;

    float *p_q, *p_WkT, *p_qk, *p_pkv, *p_attn, *p_o, *p_x, *p_h1, *p_y;
    cudaGetSymbolAddress((void**)&p_q,    g_q);
    cudaGetSymbolAddress((void**)&p_WkT,  g_WkT);
    cudaGetSymbolAddress((void**)&p_qk,   g_qk);
    cudaGetSymbolAddress((void**)&p_pkv,  g_pkv);
    cudaGetSymbolAddress((void**)&p_attn, g_attn);
    cudaGetSymbolAddress((void**)&p_o,    g_o);
    cudaGetSymbolAddress((void**)&p_x,    g_x);
    cudaGetSymbolAddress((void**)&p_h1,   g_h1);
    cudaGetSymbolAddress((void**)&p_y,    g_y);

    k_transpose_wk<<<256, 256>>>(Wk);
    k_off<<<NPOS / 8, 256>>>(hs, Woff, boff);
    // q = hs @ Wq + bq
    gemm_t<256, 0><<<dim3(128, 4, 1), 256>>>(hs, 256, 0, Wq, 256, 0,
                                             p_q, 256, 0, bq, 0, nullptr, 0);
    k_gather<<<NPOS / 4, 256>>>(emb, Wkvp, bkvp);
    // qk[a] = q[:, a*64:] @ WkT[a]   (K=64)
    gemm_t<64, 0><<<dim3(128, 4, 4), 256>>>(p_q, 256, 64, p_WkT, 256, 64 * 256,
                                            p_qk, 1024, 256, nullptr, 0, nullptr, 0);
    k_core<<<NPOS / 4, 256>>>();
    // attn[a] = pkv[a] @ Wv[:, a, :] + bv[a]
    gemm_t<256, 0><<<dim3(128, 1, 4), 256>>>(p_pkv, 1024, 256, Wv + 0, 256, 64,
                                             p_attn, 256, 64, bv, 64, nullptr, 0);
    // o = attn @ Wo + bo
    gemm_t<256, 0><<<dim3(128, 4, 1), 256>>>(p_attn, 256, 0, Wo, 256, 0,
                                             p_o, 256, 0, bo, 0, nullptr, 0);
    // x = LN1(hs + o)
    k_ln<<<NPOS / 4, 256>>>(hs, p_o, ln1s, ln1b, p_x);
    // h1 = gelu(x @ W1 + b1)
    gemm_t<256, 1><<<dim3(128, 16, 1), 256>>>(p_x, 256, 0, W1, 1024, 0,
                                              p_h1, 1024, 0, b1, 0, nullptr, 0);
    // y = x + h1 @ W2 + b2
    gemm_t<1024, 2><<<dim3(128, 4, 1), 256>>>(p_h1, 1024, 0, W2, 256, 0,
                                              p_y, 256, 0, b2, 0, p_x, 256);
    // out = LN2(y)
    k_ln<<<NPOS / 4, 256>>>(p_y, nullptr, ln2s, ln2b, out);
}

// round 11
// speedup vs baseline: 3.3654x; 1.2825x over previous
#include <cuda_runtime.h>
#include <cuda_bf16.h>
#include <math.h>

// ---------------- problem dims ----------------
#define NB 2
#define HH 64
#define WW 64
#define DD 256
#define SS 16
#define NHD 4
#define HDIM 64
#define MLPH 1024
#define NPOS (NB*HH*WW)          // 8192
#define NKV  (NPOS*SS)           // 131072

// ---------------- scratch (device globals; no allocations allowed) -------
__device__ __align__(256) float g_off [(size_t)NPOS * 32];    // transformed offsets
__device__ __align__(256) float g_q   [(size_t)NPOS * DD];    // queries [8192,256]
__device__ __align__(256) float g_WkT [4 * HDIM * DD];        // Wk transposed per head
__device__ __align__(256) float g_qk  [(size_t)NPOS * 4 * DD];// folded q·Wk^T [8192,1024]
__device__ __align__(256) float g_pkv [(size_t)NPOS * 4 * DD];// p-weighted kv [8192,1024]
__device__ __align__(256) float g_attn[(size_t)NPOS * DD];    // attn pre-Wo [8192,256]
__device__ __align__(256) float g_o   [(size_t)NPOS * DD];    // attn out [8192,256]
__device__ __align__(256) float g_x   [(size_t)NPOS * DD];    // post-LN1
__device__ __align__(256) float g_h1  [(size_t)NPOS * MLPH];  // mlp hidden
__device__ __align__(256) float g_y   [(size_t)NPOS * DD];    // pre-LN2

// ---------------- helpers ----------------
__device__ __forceinline__ float blk_sum256(float v, float* red) {
    int t = threadIdx.x;
    red[t] = v; __syncthreads();
    #pragma unroll
    for (int o = 128; o > 0; o >>= 1) {
        if (t < o) red[t] += red[t + o];
        __syncthreads();
    }
    float r = red[0]; __syncthreads();
    return r;
}

__device__ __forceinline__ float gelu_tanh(float x) {
    const float c = 0.7978845608028654f;
    float t = tanhf(c * (x + 0.044715f * x * x * x));
    return 0.5f * x * (1.f + t);
}

__device__ __forceinline__ unsigned f2tf32(float v) {
    unsigned u;
    asm("cvt.rna.tf32.f32 %0, %1;" : "=r"(u) : "f"(v));
    return u;
}

__device__ __forceinline__ void mma_tf32(float c[4], const unsigned a[4],
                                         const unsigned b[2]) {
    asm volatile(
        "mma.sync.aligned.m16n8k8.row.col.f32.tf32.tf32.f32 "
        "{%0,%1,%2,%3}, {%4,%5,%6,%7}, {%8,%9}, {%0,%1,%2,%3};\n"
        : "+f"(c[0]), "+f"(c[1]), "+f"(c[2]), "+f"(c[3])
        : "r"(a[0]), "r"(a[1]), "r"(a[2]), "r"(a[3]), "r"(b[0]), "r"(b[1]));
}

// ============================================================
// K0: transpose Wk[d, a, e] -> WkT[a][e][d]
// ============================================================
__global__ __launch_bounds__(256)
void k_transpose_wk(const float* __restrict__ Wk) {
    int o = blockIdx.x * 256 + threadIdx.x;      // 65536 total
    int d = o & 255, e = (o >> 8) & 63, a = o >> 14;
    g_WkT[o] = Wk[d * 256 + a * 64 + e];
}

// ============================================================
// K_off: offsets = 60*sigmoid(hs@Woff + boff) - 30  -> g_off [8192,32]
// ============================================================
__global__ __launch_bounds__(256)
void k_off(const float* __restrict__ hs, const float* __restrict__ Woff,
           const float* __restrict__ boff) {
    int w = threadIdx.x >> 5, j = threadIdx.x & 31;
    int p = blockIdx.x * 8 + w;
    float hreg[8];
    #pragma unroll
    for (int i = 0; i < 8; ++i) hreg[i] = hs[(size_t)p * 256 + i * 32 + j];
    float acc = 0.f;
    #pragma unroll
    for (int i = 0; i < 8; ++i)
        #pragma unroll
        for (int l = 0; l < 32; ++l) {
            float h = __shfl_sync(0xffffffffu, hreg[i], l);
            acc += h * Woff[(i * 32 + l) * 32 + j];
        }
    float sg = 1.f / (1.f + expf(-(acc + boff[j])));
    g_off[(size_t)p * 32 + j] = 60.f * sg - 30.f;
}

// ============================================================
// K_sample_core: bilinear gather (kv in SMEM only) + scores + softmax + pkv
// 4 positions per block, 256 threads
// ============================================================
__global__ __launch_bounds__(256)
void k_sample_core(const float* __restrict__ emb, const float* __restrict__ Wkvp,
                   const float* __restrict__ bkvp) {
    __shared__ float s_kv[16 * 258];
    __shared__ float s_qk[1024];
    __shared__ float s_off[32];
    __shared__ float s_w[SS][4];
    __shared__ int   s_idx[SS][4];
    __shared__ float s_sc[64];
    __shared__ float s_p[64];
    int t = threadIdx.x;
    float wkvp0 = Wkvp[t];
    float wkvp1 = Wkvp[DD + t];
    float bkv   = bkvp[t];

    for (int pp = 0; pp < 4; ++pp) {
        size_t p = (size_t)blockIdx.x * 4 + pp;
        int n  = (int)(p >> 12);
        int iy = ((int)p >> 6) & 63, jx = (int)p & 63;

        if (t < 32) s_off[t] = g_off[p * 32 + t];
        #pragma unroll
        for (int i = 0; i < 4; ++i)
            s_qk[i * 256 + t] = g_qk[p * 1024 + i * 256 + t];
        __syncthreads();

        if (t < SS) {
            int s = t;
            float y = fminf(fmaxf((float)iy + s_off[2*s    ], 0.f), 63.f);
            float x = fminf(fmaxf((float)jx + s_off[2*s + 1], 0.f), 63.f);
            float y0f = floorf(y), x0f = floorf(x);
            int y0 = (int)y0f, x0 = (int)x0f;
            int y1 = min(y0 + 1, 63), x1 = min(x0 + 1, 63);
            float wy = y - y0f, wx = x - x0f;
            s_w[s][0] = (1.f - wy) * (1.f - wx);
            s_w[s][1] = (1.f - wy) * wx;
            s_w[s][2] = wy * (1.f - wx);
            s_w[s][3] = wy * wx;
            int base = n * 4096;
            s_idx[s][0] = (base + y0 * 64 + x0) * DD;
            s_idx[s][1] = (base + y0 * 64 + x1) * DD;
            s_idx[s][2] = (base + y1 * 64 + x0) * DD;
            s_idx[s][3] = (base + y1 * 64 + x1) * DD;
        }
        __syncthreads();

        // gather kv + offset embedding -> SMEM only
        #pragma unroll 4
        for (int s = 0; s < SS; ++s) {
            float v = s_w[s][0] * emb[s_idx[s][0] + t]
                    + s_w[s][1] * emb[s_idx[s][1] + t]
                    + s_w[s][2] * emb[s_idx[s][2] + t]
                    + s_w[s][3] * emb[s_idx[s][3] + t];
            v += s_off[2*s] * wkvp0 + s_off[2*s + 1] * wkvp1 + bkv;
            s_kv[s * 258 + t] = v;
        }
        __syncthreads();

        // scores: 64 (a,s) pairs, 4 lanes per pair, interleaved d = sub + 4*i
        {
            int pair = t >> 2, sub = t & 3;
            int a = pair >> 4, s = pair & 15;
            const float* kvp = &s_kv[s * 258 + sub];
            const float* qkp = &s_qk[a * 256 + sub];
            float acc = 0.f;
            #pragma unroll 16
            for (int i = 0; i < 64; ++i) acc += qkp[i * 4] * kvp[i * 4];
            acc += __shfl_xor_sync(0xffffffffu, acc, 1);
            acc += __shfl_xor_sync(0xffffffffu, acc, 2);
            if (sub == 0) s_sc[pair] = acc * 0.125f;
        }
        __syncthreads();

        if (t < 4) {
            float mx = -1e30f;
            #pragma unroll
            for (int s = 0; s < 16; ++s) mx = fmaxf(mx, s_sc[t * 16 + s]);
            float sum = 0.f;
            float e[16];
            #pragma unroll
            for (int s = 0; s < 16; ++s) { e[s] = expf(s_sc[t * 16 + s] - mx); sum += e[s]; }
            float inv = 1.f / sum;
            #pragma unroll
            for (int s = 0; s < 16; ++s) s_p[t * 16 + s] = e[s] * inv;
        }
        __syncthreads();

        #pragma unroll
        for (int a = 0; a < 4; ++a) {
            float acc = 0.f;
            #pragma unroll
            for (int s = 0; s < 16; ++s)
                acc += s_p[a * 16 + s] * s_kv[s * 258 + t];
            g_pkv[p * 1024 + a * 256 + t] = acc;
        }
        __syncthreads();
    }
}

// ============================================================
// Generic fp32 64x64 tiled GEMM (attention-path GEMMs: q, qk, Wv, Wo)
// ============================================================
template<int KTOT, int EPI>
__global__ __launch_bounds__(256)
void gemm_t(const float* __restrict__ A, int lda, long headA,
            const float* __restrict__ B, int ldb, long headB,
            float* __restrict__ C, int ldc, long headC,
            const float* __restrict__ bias, int headBias,
            const float* __restrict__ res, int ldres) {
    A += (long)blockIdx.z * headA;
    B += (long)blockIdx.z * headB;
    C += (long)blockIdx.z * headC;
    if (bias) bias += (long)blockIdx.z * headBias;

    __shared__ float As[32][64];
    __shared__ float Bs[32][64];
    int tid = threadIdx.x;
    int tx = tid & 15, ty = tid >> 4;
    long rowBase = (long)blockIdx.x * 64;
    int  colBase = blockIdx.y * 64;
    float acc[4][4] = {};

    #pragma unroll 1
    for (int k0 = 0; k0 < KTOT; k0 += 32) {
        #pragma unroll
        for (int i = 0; i < 2; ++i) {
            int idx = tid + 256 * i;
            int m = idx >> 3, kq = (idx & 7) * 4;
            float4 a = *(const float4*)&A[(rowBase + m) * lda + k0 + kq];
            As[kq][m] = a.x; As[kq + 1][m] = a.y;
            As[kq + 2][m] = a.z; As[kq + 3][m] = a.w;
            int kb = idx >> 4, nq = (idx & 15) * 4;
            *(float4*)&Bs[kb][nq] =
                *(const float4*)&B[(long)(k0 + kb) * ldb + colBase + nq];
        }
        __syncthreads();
        #pragma unroll
        for (int k = 0; k < 32; ++k) {
            float4 a4 = *(float4*)&As[k][ty * 4];
            float4 b4 = *(float4*)&Bs[k][tx * 4];
            float av[4] = {a4.x, a4.y, a4.z, a4.w};
            float bb[4] = {b4.x, b4.y, b4.z, b4.w};
            #pragma unroll
            for (int i = 0; i < 4; ++i)
                #pragma unroll
                for (int j = 0; j < 4; ++j) acc[i][j] += av[i] * bb[j];
        }
        __syncthreads();
    }

    #pragma unroll
    for (int i = 0; i < 4; ++i) {
        long row = rowBase + ty * 4 + i;
        #pragma unroll
        for (int j = 0; j < 4; ++j) {
            int col = colBase + tx * 4 + j;
            float v = acc[i][j] + (bias ? bias[col] : 0.f);
            if (EPI == 1) v = gelu_tanh(v);
            if (EPI == 2) v += res[row * ldres + col];
            C[row * ldc + col] = v;
        }
    }
}

// ============================================================
// TF32 tensor-core GEMM (mma.sync m16n8k8) — simple smem staging.
// 128x64 block tile, BK=16. 256 thr = 8 warps (4x2), warp tile 32x32.
// A staged k-major As[k][m] (pad 132 -> fragment LDS conflict-free),
// B staged Bs[k][n] (pad 68). Fragments loaded as scalars + cvt to tf32.
// EPI: 0 = +bias, 1 = gelu(+bias), 2 = +bias+res
// ============================================================
template<int KTOT, int EPI>
__global__ __launch_bounds__(256)
void gemm_tf32(const float* __restrict__ A, const float* __restrict__ B,
               float* __restrict__ C, int N,
               const float* __restrict__ bias, const float* __restrict__ res) {
    __shared__ float As[16][132];
    __shared__ float Bs[16][68];
    int t = threadIdx.x, lane = t & 31, wid = t >> 5;
    int wm = wid >> 1, wn = wid & 1;           // 4 x 2 warp grid
    long rowBase = (long)blockIdx.x * 128;
    int  colBase = blockIdx.y * 64;
    float c[2][4][4] = {};

    int am = t >> 1, ak = (t & 1) * 8;          // A staging: row am, 8 k's
    int bk = t >> 4, bn = (t & 15) * 4;         // B staging: row bk, 4 n's
    int r = lane >> 2, kq = lane & 3;           // fragment row/col within warp

    #pragma unroll 1
    for (int k0 = 0; k0 < KTOT; k0 += 16) {
        {
            const float* arow = &A[(rowBase + am) * (long)KTOT + k0 + ak];
            float4 a0 = *(const float4*)(arow);
            float4 a1 = *(const float4*)(arow + 4);
            As[ak + 0][am] = a0.x; As[ak + 1][am] = a0.y;
            As[ak + 2][am] = a0.z; As[ak + 3][am] = a0.w;
            As[ak + 4][am] = a1.x; As[ak + 5][am] = a1.y;
            As[ak + 6][am] = a1.z; As[ak + 7][am] = a1.w;
            *(float4*)&Bs[bk][bn] =
                *(const float4*)&B[(long)(k0 + bk) * N + colBase + bn];
        }
        __syncthreads();
        #pragma unroll
        for (int ks = 0; ks < 2; ++ks) {
            int kb = ks * 8;
            unsigned af[2][4], bf[4][2];
            #pragma unroll
            for (int i = 0; i < 2; ++i) {
                int m0 = wm * 32 + i * 16;
                af[i][0] = f2tf32(As[kb + kq    ][m0 + r    ]);
                af[i][1] = f2tf32(As[kb + kq    ][m0 + r + 8]);
                af[i][2] = f2tf32(As[kb + kq + 4][m0 + r    ]);
                af[i][3] = f2tf32(As[kb + kq + 4][m0 + r + 8]);
            }
            #pragma unroll
            for (int j = 0; j < 4; ++j) {
                int n0 = wn * 32 + j * 8;
                bf[j][0] = f2tf32(Bs[kb + kq    ][n0 + r]);
                bf[j][1] = f2tf32(Bs[kb + kq + 4][n0 + r]);
            }
            #pragma unroll
            for (int i = 0; i < 2; ++i)
                #pragma unroll
                for (int j = 0; j < 4; ++j)
                    mma_tf32(c[i][j], af[i], bf[j]);
        }
        __syncthreads();
    }

    // ---- epilogue: c[i][j][e] -> C[row][col] ----
    #pragma unroll
    for (int i = 0; i < 2; ++i) {
        #pragma unroll
        for (int j = 0; j < 4; ++j) {
            long row0 = rowBase + wm * 32 + i * 16 + r;
            int  col0 = colBase + wn * 32 + j * 8 + 2 * kq;
            #pragma unroll
            for (int e = 0; e < 4; ++e) {
                long row = row0 + (e >> 1) * 8;
                int  col = col0 + (e & 1);
                float v = c[i][j][e] + bias[col];
                if (EPI == 1) v = gelu_tanh(v);
                if (EPI == 2) v += res[row * N + col];
                C[row * N + col] = v;
            }
        }
    }
}

// ============================================================
// K_ln: out = LN(xin (+ addin)) * sc + bi
// ============================================================
__global__ __launch_bounds__(256)
void k_ln(const float* __restrict__ xin, const float* __restrict__ addin,
          const float* __restrict__ sc, const float* __restrict__ bi,
          float* __restrict__ out) {
    __shared__ float red[256];
    int t = threadIdx.x;
    for (int pp = 0; pp < 4; ++pp) {
        size_t p = (size_t)blockIdx.x * 4 + pp;
        float x = xin[p * 256 + t];
        if (addin) x += addin[p * 256 + t];
        float sum  = blk_sum256(x, red);
        float sum2 = blk_sum256(x * x, red);
        float mean = sum * (1.f / 256.f);
        float var  = sum2 * (1.f / 256.f) - mean * mean;
        out[p * 256 + t] = (x - mean) * rsqrtf(var + 1e-6f) * sc[t] + bi[t];
    }
}

// ============================================================
extern "C" void kernel_launch(void* const* d_in, const int* in_sizes, int n_in,
                              void* d_out, int out_size) {
    const float* hs    = (const float*)d_in[0];
    const float* emb   = (const float*)d_in[1];
    const float* Woff  = (const float*)d_in[2];
    const float* boff  = (const float*)d_in[3];
    const float* Wkvp  = (const float*)d_in[4];
    const float* bkvp  = (const float*)d_in[5];
    const float* Wq    = (const float*)d_in[6];
    const float* bq    = (const float*)d_in[7];
    const float* Wk    = (const float*)d_in[8];
    const float* bk    = (const float*)d_in[9];   (void)bk; // softmax-invariant, folded out
    const float* Wv    = (const float*)d_in[10];
    const float* bv    = (const float*)d_in[11];
    const float* Wo    = (const float*)d_in[12];
    const float* bo    = (const float*)d_in[13];
    const float* ln1s  = (const float*)d_in[14];
    const float* ln1b  = (const float*)d_in[15];
    const float* ln2s  = (const float*)d_in[16];
    const float* ln2b  = (const float*)d_in[17];
    const float* W1    = (const float*)d_in[18];
    const float* b1    = (const float*)d_in[19];
    const float* W2    = (const float*)d_in[20];
    const float* b2    = (const float*)d_in[21];
    float* out = (float*)d_out;

    float *p_q, *p_WkT, *p_qk, *p_pkv, *p_attn, *p_o, *p_x, *p_h1, *p_y;
    cudaGetSymbolAddress((void**)&p_q,    g_q);
    cudaGetSymbolAddress((void**)&p_WkT,  g_WkT);
    cudaGetSymbolAddress((void**)&p_qk,   g_qk);
    cudaGetSymbolAddress((void**)&p_pkv,  g_pkv);
    cudaGetSymbolAddress((void**)&p_attn, g_attn);
    cudaGetSymbolAddress((void**)&p_o,    g_o);
    cudaGetSymbolAddress((void**)&p_x,    g_x);
    cudaGetSymbolAddress((void**)&p_h1,   g_h1);
    cudaGetSymbolAddress((void**)&p_y,    g_y);

    k_transpose_wk<<<256, 256>>>(Wk);
    k_off<<<NPOS / 8, 256>>>(hs, Woff, boff);
    // q = hs @ Wq + bq
    gemm_t<256, 0><<<dim3(128, 4, 1), 256>>>(hs, 256, 0, Wq, 256, 0,
                                             p_q, 256, 0, bq, 0, nullptr, 0);
    // qk[a] = q[:, a*64:] @ WkT[a]   (K=64)
    gemm_t<64, 0><<<dim3(128, 4, 4), 256>>>(p_q, 256, 64, p_WkT, 256, 64 * 256,
                                            p_qk, 1024, 256, nullptr, 0, nullptr, 0);
    // fused: gather kv (SMEM) + scores + softmax + pkv
    k_sample_core<<<NPOS / 4, 256>>>(emb, Wkvp, bkvp);
    // attn[a] = pkv[a] @ Wv[:, a, :] + bv[a]
    gemm_t<256, 0><<<dim3(128, 1, 4), 256>>>(p_pkv, 1024, 256, Wv, 256, 64,
                                             p_attn, 256, 64, bv, 64, nullptr, 0);
    // o = attn @ Wo + bo
    gemm_t<256, 0><<<dim3(128, 4, 1), 256>>>(p_attn, 256, 0, Wo, 256, 0,
                                             p_o, 256, 0, bo, 0, nullptr, 0);
    // x = LN1(hs + o)
    k_ln<<<NPOS / 4, 256>>>(hs, p_o, ln1s, ln1b, p_x);
    // h1 = gelu(x @ W1 + b1)   [tf32 tensor cores]
    gemm_tf32<256, 1><<<dim3(64, 16), 256>>>(p_x, W1, p_h1, 1024, b1, nullptr);
    // y = x + h1 @ W2 + b2     [tf32 tensor cores]
    gemm_tf32<1024, 2><<<dim3(64, 4), 256>>>(p_h1, W2, p_y, 256, b2, p_x);
    // out = LN2(y)
    k_ln<<<NPOS / 4, 256>>>(p_y, nullptr, ln2s, ln2b, out);
}

// round 12
// speedup vs baseline: 3.3843x; 1.0056x over previous
#include <cuda_runtime.h>
#include <cuda_bf16.h>
#include <math.h>

// ---------------- problem dims ----------------
#define NB 2
#define HH 64
#define WW 64
#define DD 256
#define SS 16
#define NHD 4
#define HDIM 64
#define MLPH 1024
#define NPOS (NB*HH*WW)          // 8192
#define NKV  (NPOS*SS)           // 131072

// ---------------- scratch (device globals; no allocations allowed) -------
__device__ __align__(256) float g_off [(size_t)NPOS * 32];    // transformed offsets
__device__ __align__(256) float g_WkT [4 * HDIM * DD];        // Wk transposed per head
__device__ __align__(256) float g_Wqk [DD * 4 * DD];          // folded Wq·Wk^T [256,1024]
__device__ __align__(256) float g_Wvo [4 * DD * DD];          // folded Wv·Wo   [1024,256]
__device__ __align__(256) float g_bqk [4 * DD];               // folded bq·Wk^T [1024]
__device__ __align__(256) float g_bvo [DD];                   // folded bo+bv·Wo [256]
__device__ __align__(256) float g_qk  [(size_t)NPOS * 4 * DD];// hs·Wqk [8192,1024]
__device__ __align__(256) float g_pkv [(size_t)NPOS * 4 * DD];// p-weighted kv [8192,1024]
__device__ __align__(256) float g_o   [(size_t)NPOS * DD];    // attn out [8192,256]
__device__ __align__(256) float g_x   [(size_t)NPOS * DD];    // post-LN1
__device__ __align__(256) float g_h1  [(size_t)NPOS * MLPH];  // mlp hidden
__device__ __align__(256) float g_y   [(size_t)NPOS * DD];    // pre-LN2

// ---------------- helpers ----------------
__device__ __forceinline__ float blk_sum256(float v, float* red) {
    int t = threadIdx.x;
    red[t] = v; __syncthreads();
    #pragma unroll
    for (int o = 128; o > 0; o >>= 1) {
        if (t < o) red[t] += red[t + o];
        __syncthreads();
    }
    float r = red[0]; __syncthreads();
    return r;
}

__device__ __forceinline__ float gelu_tanh(float x) {
    const float c = 0.7978845608028654f;
    float t = tanhf(c * (x + 0.044715f * x * x * x));
    return 0.5f * x * (1.f + t);
}

__device__ __forceinline__ unsigned f2tf32(float v) {
    unsigned u;
    asm("cvt.rna.tf32.f32 %0, %1;" : "=r"(u) : "f"(v));
    return u;
}

__device__ __forceinline__ void mma_tf32(float c[4], const unsigned a[4],
                                         const unsigned b[2]) {
    asm volatile(
        "mma.sync.aligned.m16n8k8.row.col.f32.tf32.tf32.f32 "
        "{%0,%1,%2,%3}, {%4,%5,%6,%7}, {%8,%9}, {%0,%1,%2,%3};\n"
        : "+f"(c[0]), "+f"(c[1]), "+f"(c[2]), "+f"(c[3])
        : "r"(a[0]), "r"(a[1]), "r"(a[2]), "r"(a[3]), "r"(b[0]), "r"(b[1]));
}

// ============================================================
// K0: transpose Wk[d, a, e] -> WkT[a][e][d]
// ============================================================
__global__ __launch_bounds__(256)
void k_transpose_wk(const float* __restrict__ Wk) {
    int o = blockIdx.x * 256 + threadIdx.x;      // 65536 total
    int d = o & 255, e = (o >> 8) & 63, a = o >> 14;
    g_WkT[o] = Wk[d * 256 + a * 64 + e];
}

// ============================================================
// K_fold_bias: bvo[d] = bo[d] + sum_ae bv[ae]*Wo[ae][d]
//              bqk[a*256+d] = sum_e bq[a*64+e]*WkT[a][e][d]
// ============================================================
__global__ __launch_bounds__(256)
void k_fold_bias(const float* __restrict__ bq, const float* __restrict__ bv,
                 const float* __restrict__ Wo, const float* __restrict__ bo) {
    int t = threadIdx.x;
    if (blockIdx.x == 0) {
        float acc = bo[t];
        #pragma unroll 8
        for (int ae = 0; ae < 256; ++ae) acc += bv[ae] * Wo[ae * 256 + t];
        g_bvo[t] = acc;
    } else {
        for (int r = 0; r < 4; ++r) {
            int j = r * 256 + t;
            int a = j >> 8, d = j & 255;
            float acc = 0.f;
            #pragma unroll 8
            for (int e = 0; e < 64; ++e)
                acc += bq[a * 64 + e] * g_WkT[a * 16384 + e * 256 + d];
            g_bqk[j] = acc;
        }
    }
}

// ============================================================
// K_off: offsets = 60*sigmoid(hs@Woff + boff) - 30  -> g_off [8192,32]
// ============================================================
__global__ __launch_bounds__(256)
void k_off(const float* __restrict__ hs, const float* __restrict__ Woff,
           const float* __restrict__ boff) {
    int w = threadIdx.x >> 5, j = threadIdx.x & 31;
    int p = blockIdx.x * 8 + w;
    float hreg[8];
    #pragma unroll
    for (int i = 0; i < 8; ++i) hreg[i] = hs[(size_t)p * 256 + i * 32 + j];
    float acc = 0.f;
    #pragma unroll
    for (int i = 0; i < 8; ++i)
        #pragma unroll
        for (int l = 0; l < 32; ++l) {
            float h = __shfl_sync(0xffffffffu, hreg[i], l);
            acc += h * Woff[(i * 32 + l) * 32 + j];
        }
    float sg = 1.f / (1.f + expf(-(acc + boff[j])));
    g_off[(size_t)p * 32 + j] = 60.f * sg - 30.f;
}

// ============================================================
// K_sample_core: bilinear gather (kv in SMEM only) + scores + softmax + pkv
// 4 positions per block, 256 threads
// ============================================================
__global__ __launch_bounds__(256)
void k_sample_core(const float* __restrict__ emb, const float* __restrict__ Wkvp,
                   const float* __restrict__ bkvp) {
    __shared__ float s_kv[16 * 258];
    __shared__ float s_qk[1024];
    __shared__ float s_off[32];
    __shared__ float s_w[SS][4];
    __shared__ int   s_idx[SS][4];
    __shared__ float s_sc[64];
    __shared__ float s_p[64];
    int t = threadIdx.x;
    float wkvp0 = Wkvp[t];
    float wkvp1 = Wkvp[DD + t];
    float bkv   = bkvp[t];

    for (int pp = 0; pp < 4; ++pp) {
        size_t p = (size_t)blockIdx.x * 4 + pp;
        int n  = (int)(p >> 12);
        int iy = ((int)p >> 6) & 63, jx = (int)p & 63;

        if (t < 32) s_off[t] = g_off[p * 32 + t];
        #pragma unroll
        for (int i = 0; i < 4; ++i)
            s_qk[i * 256 + t] = g_qk[p * 1024 + i * 256 + t];
        __syncthreads();

        if (t < SS) {
            int s = t;
            float y = fminf(fmaxf((float)iy + s_off[2*s    ], 0.f), 63.f);
            float x = fminf(fmaxf((float)jx + s_off[2*s + 1], 0.f), 63.f);
            float y0f = floorf(y), x0f = floorf(x);
            int y0 = (int)y0f, x0 = (int)x0f;
            int y1 = min(y0 + 1, 63), x1 = min(x0 + 1, 63);
            float wy = y - y0f, wx = x - x0f;
            s_w[s][0] = (1.f - wy) * (1.f - wx);
            s_w[s][1] = (1.f - wy) * wx;
            s_w[s][2] = wy * (1.f - wx);
            s_w[s][3] = wy * wx;
            int base = n * 4096;
            s_idx[s][0] = (base + y0 * 64 + x0) * DD;
            s_idx[s][1] = (base + y0 * 64 + x1) * DD;
            s_idx[s][2] = (base + y1 * 64 + x0) * DD;
            s_idx[s][3] = (base + y1 * 64 + x1) * DD;
        }
        __syncthreads();

        // gather kv + offset embedding -> SMEM only
        #pragma unroll 4
        for (int s = 0; s < SS; ++s) {
            float v = s_w[s][0] * emb[s_idx[s][0] + t]
                    + s_w[s][1] * emb[s_idx[s][1] + t]
                    + s_w[s][2] * emb[s_idx[s][2] + t]
                    + s_w[s][3] * emb[s_idx[s][3] + t];
            v += s_off[2*s] * wkvp0 + s_off[2*s + 1] * wkvp1 + bkv;
            s_kv[s * 258 + t] = v;
        }
        __syncthreads();

        // scores: 64 (a,s) pairs, 4 lanes per pair, interleaved d = sub + 4*i
        {
            int pair = t >> 2, sub = t & 3;
            int a = pair >> 4, s = pair & 15;
            const float* kvp = &s_kv[s * 258 + sub];
            const float* qkp = &s_qk[a * 256 + sub];
            float acc = 0.f;
            #pragma unroll 16
            for (int i = 0; i < 64; ++i) acc += qkp[i * 4] * kvp[i * 4];
            acc += __shfl_xor_sync(0xffffffffu, acc, 1);
            acc += __shfl_xor_sync(0xffffffffu, acc, 2);
            if (sub == 0) s_sc[pair] = acc * 0.125f;
        }
        __syncthreads();

        if (t < 4) {
            float mx = -1e30f;
            #pragma unroll
            for (int s = 0; s < 16; ++s) mx = fmaxf(mx, s_sc[t * 16 + s]);
            float sum = 0.f;
            float e[16];
            #pragma unroll
            for (int s = 0; s < 16; ++s) { e[s] = expf(s_sc[t * 16 + s] - mx); sum += e[s]; }
            float inv = 1.f / sum;
            #pragma unroll
            for (int s = 0; s < 16; ++s) s_p[t * 16 + s] = e[s] * inv;
        }
        __syncthreads();

        #pragma unroll
        for (int a = 0; a < 4; ++a) {
            float acc = 0.f;
            #pragma unroll
            for (int s = 0; s < 16; ++s)
                acc += s_p[a * 16 + s] * s_kv[s * 258 + t];
            g_pkv[p * 1024 + a * 256 + t] = acc;
        }
        __syncthreads();
    }
}

// ============================================================
// Generic fp32 64x64 tiled GEMM (weight precompute only)
// ============================================================
template<int KTOT, int EPI>
__global__ __launch_bounds__(256)
void gemm_t(const float* __restrict__ A, int lda, long headA,
            const float* __restrict__ B, int ldb, long headB,
            float* __restrict__ C, int ldc, long headC,
            const float* __restrict__ bias, int headBias,
            const float* __restrict__ res, int ldres) {
    A += (long)blockIdx.z * headA;
    B += (long)blockIdx.z * headB;
    C += (long)blockIdx.z * headC;
    if (bias) bias += (long)blockIdx.z * headBias;

    __shared__ float As[32][64];
    __shared__ float Bs[32][64];
    int tid = threadIdx.x;
    int tx = tid & 15, ty = tid >> 4;
    long rowBase = (long)blockIdx.x * 64;
    int  colBase = blockIdx.y * 64;
    float acc[4][4] = {};

    #pragma unroll 1
    for (int k0 = 0; k0 < KTOT; k0 += 32) {
        #pragma unroll
        for (int i = 0; i < 2; ++i) {
            int idx = tid + 256 * i;
            int m = idx >> 3, kq = (idx & 7) * 4;
            float4 a = *(const float4*)&A[(rowBase + m) * lda + k0 + kq];
            As[kq][m] = a.x; As[kq + 1][m] = a.y;
            As[kq + 2][m] = a.z; As[kq + 3][m] = a.w;
            int kb = idx >> 4, nq = (idx & 15) * 4;
            *(float4*)&Bs[kb][nq] =
                *(const float4*)&B[(long)(k0 + kb) * ldb + colBase + nq];
        }
        __syncthreads();
        #pragma unroll
        for (int k = 0; k < 32; ++k) {
            float4 a4 = *(float4*)&As[k][ty * 4];
            float4 b4 = *(float4*)&Bs[k][tx * 4];
            float av[4] = {a4.x, a4.y, a4.z, a4.w};
            float bb[4] = {b4.x, b4.y, b4.z, b4.w};
            #pragma unroll
            for (int i = 0; i < 4; ++i)
                #pragma unroll
                for (int j = 0; j < 4; ++j) acc[i][j] += av[i] * bb[j];
        }
        __syncthreads();
    }

    #pragma unroll
    for (int i = 0; i < 4; ++i) {
        long row = rowBase + ty * 4 + i;
        #pragma unroll
        for (int j = 0; j < 4; ++j) {
            int col = colBase + tx * 4 + j;
            float v = acc[i][j] + (bias ? bias[col] : 0.f);
            if (EPI == 1) v = gelu_tanh(v);
            if (EPI == 2) v += res[row * ldres + col];
            C[row * ldc + col] = v;
        }
    }
}

// ============================================================
// TF32 tensor-core GEMM (mma.sync m16n8k8) — simple smem staging.
// 128x64 block tile, BK=16. 256 thr = 8 warps (4x2), warp tile 32x32.
// EPI: 0 = +bias, 1 = gelu(+bias), 2 = +bias+res
// ============================================================
template<int KTOT, int EPI>
__global__ __launch_bounds__(256)
void gemm_tf32(const float* __restrict__ A, const float* __restrict__ B,
               float* __restrict__ C, int N,
               const float* __restrict__ bias, const float* __restrict__ res) {
    __shared__ float As[16][132];
    __shared__ float Bs[16][68];
    int t = threadIdx.x, lane = t & 31, wid = t >> 5;
    int wm = wid >> 1, wn = wid & 1;           // 4 x 2 warp grid
    long rowBase = (long)blockIdx.x * 128;
    int  colBase = blockIdx.y * 64;
    float c[2][4][4] = {};

    int am = t >> 1, ak = (t & 1) * 8;          // A staging: row am, 8 k's
    int bk = t >> 4, bn = (t & 15) * 4;         // B staging: row bk, 4 n's
    int r = lane >> 2, kq = lane & 3;           // fragment row/col within warp

    #pragma unroll 1
    for (int k0 = 0; k0 < KTOT; k0 += 16) {
        {
            const float* arow = &A[(rowBase + am) * (long)KTOT + k0 + ak];
            float4 a0 = *(const float4*)(arow);
            float4 a1 = *(const float4*)(arow + 4);
            As[ak + 0][am] = a0.x; As[ak + 1][am] = a0.y;
            As[ak + 2][am] = a0.z; As[ak + 3][am] = a0.w;
            As[ak + 4][am] = a1.x; As[ak + 5][am] = a1.y;
            As[ak + 6][am] = a1.z; As[ak + 7][am] = a1.w;
            *(float4*)&Bs[bk][bn] =
                *(const float4*)&B[(long)(k0 + bk) * N + colBase + bn];
        }
        __syncthreads();
        #pragma unroll
        for (int ks = 0; ks < 2; ++ks) {
            int kb = ks * 8;
            unsigned af[2][4], bf[4][2];
            #pragma unroll
            for (int i = 0; i < 2; ++i) {
                int m0 = wm * 32 + i * 16;
                af[i][0] = f2tf32(As[kb + kq    ][m0 + r    ]);
                af[i][1] = f2tf32(As[kb + kq    ][m0 + r + 8]);
                af[i][2] = f2tf32(As[kb + kq + 4][m0 + r    ]);
                af[i][3] = f2tf32(As[kb + kq + 4][m0 + r + 8]);
            }
            #pragma unroll
            for (int j = 0; j < 4; ++j) {
                int n0 = wn * 32 + j * 8;
                bf[j][0] = f2tf32(Bs[kb + kq    ][n0 + r]);
                bf[j][1] = f2tf32(Bs[kb + kq + 4][n0 + r]);
            }
            #pragma unroll
            for (int i = 0; i < 2; ++i)
                #pragma unroll
                for (int j = 0; j < 4; ++j)
                    mma_tf32(c[i][j], af[i], bf[j]);
        }
        __syncthreads();
    }

    // ---- epilogue: c[i][j][e] -> C[row][col] ----
    #pragma unroll
    for (int i = 0; i < 2; ++i) {
        #pragma unroll
        for (int j = 0; j < 4; ++j) {
            long row0 = rowBase + wm * 32 + i * 16 + r;
            int  col0 = colBase + wn * 32 + j * 8 + 2 * kq;
            #pragma unroll
            for (int e = 0; e < 4; ++e) {
                long row = row0 + (e >> 1) * 8;
                int  col = col0 + (e & 1);
                float v = c[i][j][e] + bias[col];
                if (EPI == 1) v = gelu_tanh(v);
                if (EPI == 2) v += res[row * N + col];
                C[row * N + col] = v;
            }
        }
    }
}

// ============================================================
// K_ln: out = LN(xin (+ addin)) * sc + bi
// ============================================================
__global__ __launch_bounds__(256)
void k_ln(const float* __restrict__ xin, const float* __restrict__ addin,
          const float* __restrict__ sc, const float* __restrict__ bi,
          float* __restrict__ out) {
    __shared__ float red[256];
    int t = threadIdx.x;
    for (int pp = 0; pp < 4; ++pp) {
        size_t p = (size_t)blockIdx.x * 4 + pp;
        float x = xin[p * 256 + t];
        if (addin) x += addin[p * 256 + t];
        float sum  = blk_sum256(x, red);
        float sum2 = blk_sum256(x * x, red);
        float mean = sum * (1.f / 256.f);
        float var  = sum2 * (1.f / 256.f) - mean * mean;
        out[p * 256 + t] = (x - mean) * rsqrtf(var + 1e-6f) * sc[t] + bi[t];
    }
}

// ============================================================
extern "C" void kernel_launch(void* const* d_in, const int* in_sizes, int n_in,
                              void* d_out, int out_size) {
    const float* hs    = (const float*)d_in[0];
    const float* emb   = (const float*)d_in[1];
    const float* Woff  = (const float*)d_in[2];
    const float* boff  = (const float*)d_in[3];
    const float* Wkvp  = (const float*)d_in[4];
    const float* bkvp  = (const float*)d_in[5];
    const float* Wq    = (const float*)d_in[6];
    const float* bq    = (const float*)d_in[7];
    const float* Wk    = (const float*)d_in[8];
    const float* bk    = (const float*)d_in[9];   (void)bk; // softmax-invariant, folded out
    const float* Wv    = (const float*)d_in[10];
    const float* bv    = (const float*)d_in[11];
    const float* Wo    = (const float*)d_in[12];
    const float* bo    = (const float*)d_in[13];
    const float* ln1s  = (const float*)d_in[14];
    const float* ln1b  = (const float*)d_in[15];
    const float* ln2s  = (const float*)d_in[16];
    const float* ln2b  = (const float*)d_in[17];
    const float* W1    = (const float*)d_in[18];
    const float* b1    = (const float*)d_in[19];
    const float* W2    = (const float*)d_in[20];
    const float* b2    = (const float*)d_in[21];
    float* out = (float*)d_out;

    float *p_WkT, *p_Wqk, *p_Wvo, *p_bqk, *p_bvo;
    float *p_qk, *p_pkv, *p_o, *p_x, *p_h1, *p_y;
    cudaGetSymbolAddress((void**)&p_WkT,  g_WkT);
    cudaGetSymbolAddress((void**)&p_Wqk,  g_Wqk);
    cudaGetSymbolAddress((void**)&p_Wvo,  g_Wvo);
    cudaGetSymbolAddress((void**)&p_bqk,  g_bqk);
    cudaGetSymbolAddress((void**)&p_bvo,  g_bvo);
    cudaGetSymbolAddress((void**)&p_qk,   g_qk);
    cudaGetSymbolAddress((void**)&p_pkv,  g_pkv);
    cudaGetSymbolAddress((void**)&p_o,    g_o);
    cudaGetSymbolAddress((void**)&p_x,    g_x);
    cudaGetSymbolAddress((void**)&p_h1,   g_h1);
    cudaGetSymbolAddress((void**)&p_y,    g_y);

    // ---- one-time weight folding ----
    k_transpose_wk<<<256, 256>>>(Wk);
    // Wqk[dd, a*256+d] = sum_e Wq[dd, a*64+e] * WkT[a][e][d]
    gemm_t<64, 0><<<dim3(4, 4, 4), 256>>>(Wq, 256, 64, p_WkT, 256, 64 * 256,
                                          p_Wqk, 1024, 256, nullptr, 0, nullptr, 0);
    // Wvo[a*256+dd, d] = sum_e Wv[dd, a*64+e] * Wo[(a*64+e)*256 + d]
    gemm_t<64, 0><<<dim3(4, 4, 4), 256>>>(Wv, 256, 64, Wo, 256, 64 * 256,
                                          p_Wvo, 256, 256 * 256, nullptr, 0, nullptr, 0);
    k_fold_bias<<<2, 256>>>(bq, bv, Wo, bo);

    // ---- main pipeline ----
    k_off<<<NPOS / 8, 256>>>(hs, Woff, boff);
    // qk = hs @ Wqk + bqk   [tf32]
    gemm_tf32<256, 0><<<dim3(64, 16), 256>>>(hs, p_Wqk, p_qk, 1024, p_bqk, nullptr);
    // fused: gather kv (SMEM) + scores + softmax + pkv
    k_sample_core<<<NPOS / 4, 256>>>(emb, Wkvp, bkvp);
    // o = pkv @ Wvo + bvo   [tf32]
    gemm_tf32<1024, 0><<<dim3(64, 4), 256>>>(p_pkv, p_Wvo, p_o, 256, p_bvo, nullptr);
    // x = LN1(hs + o)
    k_ln<<<NPOS / 4, 256>>>(hs, p_o, ln1s, ln1b, p_x);
    // h1 = gelu(x @ W1 + b1)   [tf32]
    gemm_tf32<256, 1><<<dim3(64, 16), 256>>>(p_x, W1, p_h1, 1024, b1, nullptr);
    // y = x + h1 @ W2 + b2     [tf32]
    gemm_tf32<1024, 2><<<dim3(64, 4), 256>>>(p_h1, W2, p_y, 256, b2, p_x);
    // out = LN2(y)
    k_ln<<<NPOS / 4, 256>>>(p_y, nullptr, ln2s, ln2b, out);
}